// round 1
// baseline (speedup 1.0000x reference)
#include <cuda_runtime.h>

#define DD   256
#define E2   512
#define NT   128
#define NF   128
#define NBN  16
#define SROW 516
#define EPS  1e-5f

// ---------------- scratch (device globals; no allocation allowed) ----------
__device__ float g_cx[NBN * DD];
__device__ float g_ct[NT * DD];
__device__ float g_cf[NF * DD];
__device__ float g_qx[NBN];
__device__ float g_qt[NT];
__device__ float g_qf[NF];
__device__ float g_dxt[NBN * NT];
__device__ float g_dxf[NBN * NF];
__device__ float g_dtf[NT * NF];
__device__ float g_ux[NBN * E2];
__device__ float g_ut[NT * E2];
__device__ float g_uf[NF * E2];
__device__ float g_c[E2];

// ---------------- P1: center each embedding row, store centered + sq-norm --
__global__ void k_center(const float* __restrict__ x,
                         const float* __restrict__ t_emb,
                         const float* __restrict__ f_emb) {
    __shared__ float red[8];
    __shared__ float s_mu;
    int r = blockIdx.x;
    const float* src;
    float* dst;
    float* q;
    if (r < 16)       { src = x + r * DD;            dst = g_cx + r * DD;        q = g_qx + r; }
    else if (r < 144) { int i = r - 16;  src = t_emb + i * DD; dst = g_ct + i * DD; q = g_qt + i; }
    else              { int i = r - 144; src = f_emb + i * DD; dst = g_cf + i * DD; q = g_qf + i; }

    int tid = threadIdx.x;
    float v = src[tid];

    // mean
    float s = v;
    #pragma unroll
    for (int o = 16; o; o >>= 1) s += __shfl_xor_sync(0xffffffffu, s, o);
    if ((tid & 31) == 0) red[tid >> 5] = s;
    __syncthreads();
    if (tid == 0) {
        float tot = 0.f;
        #pragma unroll
        for (int i = 0; i < 8; i++) tot += red[i];
        s_mu = tot * (1.0f / DD);
    }
    __syncthreads();

    float c = v - s_mu;
    dst[tid] = c;

    // squared norm
    s = c * c;
    #pragma unroll
    for (int o = 16; o; o >>= 1) s += __shfl_xor_sync(0xffffffffu, s, o);
    __syncthreads();            // protect red[] reuse
    if ((tid & 31) == 0) red[tid >> 5] = s;
    __syncthreads();
    if (tid == 0) {
        float tot = 0.f;
        #pragma unroll
        for (int i = 0; i < 8; i++) tot += red[i];
        *q = tot;
    }
}

// ---------------- P2: pairwise dot products (one warp per dot) -------------
__global__ void k_dots() {
    int w    = (blockIdx.x * blockDim.x + threadIdx.x) >> 5;
    int lane = threadIdx.x & 31;
    const float *a, *b;
    float* dst;
    if (w < 2048) {                 // cx . ct
        int i = w >> 7, j = w & 127;
        a = g_cx + i * DD; b = g_ct + j * DD; dst = g_dxt + w;
    } else if (w < 4096) {          // cx . cf
        int w2 = w - 2048;
        int i = w2 >> 7, j = w2 & 127;
        a = g_cx + i * DD; b = g_cf + j * DD; dst = g_dxf + w2;
    } else {                        // ct . cf
        int w3 = w - 4096;
        a = g_ct + (w3 >> 7) * DD; b = g_cf + (w3 & 127) * DD; dst = g_dtf + w3;
    }
    const float4* a4 = (const float4*)a;
    const float4* b4 = (const float4*)b;
    float s = 0.f;
    #pragma unroll
    for (int j = 0; j < 2; j++) {
        float4 av = a4[lane * 2 + j];
        float4 bv = b4[lane * 2 + j];
        s += av.x * bv.x + av.y * bv.y + av.z * bv.z + av.w * bv.w;
    }
    #pragma unroll
    for (int o = 16; o; o >>= 1) s += __shfl_xor_sync(0xffffffffu, s, o);
    if (lane == 0) *dst = s;
}

// ---------------- P3: project 272 centered (⊙g) rows + ln_b row through W1 -
__global__ void k_project(const float* __restrict__ ln_g,
                          const float* __restrict__ ln_b,
                          const float* __restrict__ W1,
                          const float* __restrict__ b1) {
    __shared__ float cg[DD];
    int r = blockIdx.x;
    int e = threadIdx.x;   // 512 threads
    if (e < DD) {
        float c;
        float g = ln_g[e];
        if (r < 16)       c = g_cx[r * DD + e];
        else if (r < 144) c = g_ct[(r - 16) * DD + e];
        else if (r < 272) c = g_cf[(r - 144) * DD + e];
        else              { c = ln_b[e]; g = 1.0f; }
        cg[e] = c * g;
    }
    __syncthreads();
    float acc = 0.f;
    #pragma unroll 8
    for (int k = 0; k < DD; k++)
        acc = fmaf(cg[k], W1[k * E2 + e], acc);
    if (r < 16)       g_ux[r * E2 + e] = acc;
    else if (r < 144) g_ut[(r - 16) * E2 + e] = acc;
    else if (r < 272) g_uf[(r - 144) * E2 + e] = acc;
    else              g_c[e] = acc + b1[e];
}

// ---------------- main: per-row rinv + fused ReLU-MLP epilogue -------------
__global__ void __launch_bounds__(256, 3)
k_main(const float* __restrict__ W2, const float* __restrict__ b2,
       float* __restrict__ out) {
    extern __shared__ float sm[];
    float* s_tf = sm;                 // [16][SROW]  u_t + u_f (f-local rows)
    float* s_ux = sm + 16 * SROW;     // [16][SROW]  u_x (bn rows)
    float* s_c  = sm + 32 * SROW;     // [512]
    float* s_w0 = s_c + E2;           // [512]
    float* s_w1 = s_w0 + E2;          // [512]

    int t   = blockIdx.x;
    int fb  = blockIdx.y;
    int tid = threadIdx.x;
    int bn  = tid >> 4;
    int fl  = tid & 15;
    int f   = fb * 16 + fl;

    // fill smem (coalesced global reads, conflict-free writes)
    for (int i = tid; i < 16 * E2; i += 256) {
        int r = i >> 9, e = i & 511;
        s_tf[r * SROW + e] = g_ut[t * E2 + e] + g_uf[(fb * 16 + r) * E2 + e];
        s_ux[r * SROW + e] = g_ux[r * E2 + e];
    }
    for (int i = tid; i < E2; i += 256) {
        s_c[i]  = g_c[i];
        s_w0[i] = W2[2 * i];
        s_w1[i] = W2[2 * i + 1];
    }

    // variance from decomposed terms
    float var = (g_qx[bn] + g_qt[t] + g_qf[f]
                 + 2.0f * (g_dxt[bn * 128 + t] + g_dxf[bn * 128 + f] + g_dtf[t * 128 + f]))
                * (1.0f / 256.0f);
    float rinv = rsqrtf(var + EPS);
    __syncthreads();

    const float4* ptf = (const float4*)(s_tf + fl * SROW);
    const float4* pux = (const float4*)(s_ux + bn * SROW);
    const float4* pc  = (const float4*)s_c;
    const float4* pw0 = (const float4*)s_w0;
    const float4* pw1 = (const float4*)s_w1;

    float a0 = 0.f, a1 = 0.f;
    #pragma unroll 8
    for (int e4 = 0; e4 < 128; e4++) {
        float4 s  = ptf[e4];
        float4 u  = pux[e4];
        float4 c  = pc[e4];
        float4 w0 = pw0[e4];
        float4 w1 = pw1[e4];
        float z;
        z = fmaxf(fmaf(rinv, s.x + u.x, c.x), 0.f); a0 = fmaf(z, w0.x, a0); a1 = fmaf(z, w1.x, a1);
        z = fmaxf(fmaf(rinv, s.y + u.y, c.y), 0.f); a0 = fmaf(z, w0.y, a0); a1 = fmaf(z, w1.y, a1);
        z = fmaxf(fmaf(rinv, s.z + u.z, c.z), 0.f); a0 = fmaf(z, w0.z, a0); a1 = fmaf(z, w1.z, a1);
        z = fmaxf(fmaf(rinv, s.w + u.w, c.w), 0.f); a0 = fmaf(z, w0.w, a0); a1 = fmaf(z, w1.w, a1);
    }

    int row = (bn * NT + t) * NF + f;
    float2 o2 = make_float2(a0 + b2[0], a1 + b2[1]);
    ((float2*)out)[row] = o2;
}

// ---------------- launch ----------------------------------------------------
extern "C" void kernel_launch(void* const* d_in, const int* in_sizes, int n_in,
                              void* d_out, int out_size) {
    const float* x     = (const float*)d_in[0];
    const float* t_emb = (const float*)d_in[1];
    const float* f_emb = (const float*)d_in[2];
    const float* ln_g  = (const float*)d_in[3];
    const float* ln_b  = (const float*)d_in[4];
    const float* W1    = (const float*)d_in[5];
    const float* b1    = (const float*)d_in[6];
    const float* W2    = (const float*)d_in[7];
    const float* b2    = (const float*)d_in[8];
    float* out = (float*)d_out;

    const int smem_bytes = (32 * SROW + 3 * E2) * (int)sizeof(float);  // 72192
    cudaFuncSetAttribute(k_main, cudaFuncAttributeMaxDynamicSharedMemorySize, smem_bytes);

    k_center<<<272, 256>>>(x, t_emb, f_emb);
    k_dots<<<2560, 256>>>();
    k_project<<<273, 512>>>(ln_g, ln_b, W1, b1);
    dim3 grid(NT, 8);
    k_main<<<grid, 256, smem_bytes>>>(W2, b2, out);
}